// round 16
// baseline (speedup 1.0000x reference)
#include <cuda_runtime.h>
#include <math.h>

#define DIMX 128
#define DIMY 128
#define DIMZ 64
#define SY   128
#define SZ   16384
#define VOL  1048576           // DIMZ*DIMY*DIMX
#define NTOT 2097152           // 2 * VOL
#define TPB  256
#define NBLK (NTOT / TPB)      // 8192
#define N4    (NTOT / 4)       // 524288
#define NBLK4 (N4 / TPB)       // 2048

// 17 fields of NTOT floats:
// 0 P | 1 Y | 2 Hd | 3 S1 | 4 S2 | 5 S3
// 6 EA0 | 7 EA1 | 8 EA2 | 9 EB0 | 10 EB1 | 11 EB2 | 12..14 spare | 15 D1 | 16 D2
__device__ __align__(16) float g_buf[17u * (size_t)NTOT];
__device__ double   g_acc[16];
__device__ unsigned g_mm[8];

#define PINF __int_as_float(0x7f800000)
#define NINF __int_as_float(0xff800000)

// ---------------------------------------------------------------- helpers
__device__ __forceinline__ float hmax4(float4 a) { return fmaxf(fmaxf(a.x, a.y), fmaxf(a.z, a.w)); }
__device__ __forceinline__ float hmin4(float4 a) { return fminf(fminf(a.x, a.y), fminf(a.z, a.w)); }

// ---------------------------------------------------------------- reductions
__device__ __forceinline__ void block_add(double v, double* dst) {
    __shared__ double s_red[8];
#pragma unroll
    for (int o = 16; o > 0; o >>= 1) v += __shfl_down_sync(0xffffffffu, v, o);
    int lane = threadIdx.x & 31, wrp = threadIdx.x >> 5;
    if (lane == 0) s_red[wrp] = v;
    __syncthreads();
    if (threadIdx.x == 0) {
        double s = s_red[0];
#pragma unroll
        for (int k = 1; k < 8; ++k) s += s_red[k];
        atomicAdd(dst, s);
    }
    __syncthreads();
}

__device__ __forceinline__ void block_max_to(float v, unsigned* dst) {
    __shared__ float s_mx[8];
#pragma unroll
    for (int o = 16; o > 0; o >>= 1) v = fmaxf(v, __shfl_down_sync(0xffffffffu, v, o));
    int lane = threadIdx.x & 31, wrp = threadIdx.x >> 5;
    if (lane == 0) s_mx[wrp] = v;
    __syncthreads();
    if (threadIdx.x == 0) {
        float m = s_mx[0];
#pragma unroll
        for (int k = 1; k < 8; ++k) m = fmaxf(m, s_mx[k]);
        atomicMax(dst, __float_as_uint(m));
    }
    __syncthreads();
}

__device__ __forceinline__ void block_min_to(float v, unsigned* dst) {
    __shared__ float s_mn[8];
#pragma unroll
    for (int o = 16; o > 0; o >>= 1) v = fminf(v, __shfl_down_sync(0xffffffffu, v, o));
    int lane = threadIdx.x & 31, wrp = threadIdx.x >> 5;
    if (lane == 0) s_mn[wrp] = v;
    __syncthreads();
    if (threadIdx.x == 0) {
        float m = s_mn[0];
#pragma unroll
        for (int k = 1; k < 8; ++k) m = fminf(m, s_mn[k]);
        atomicMin(dst, __float_as_uint(m));
    }
    __syncthreads();
}

// ---------------------------------------------------------------- init
__global__ void k_init() {
    int t = threadIdx.x;
    if (t < 16) g_acc[t] = 0.0;
    if (t < 8)  g_mm[t] = (t == 2 || t == 3 || t == 6 || t == 7) ? 0x7F800000u : 0u;
}

// ---------------------------------------------------------------- fused prep + directional
__global__ void __launch_bounds__(TPB) k_prep_dir(const float* __restrict__ net,
                                                  const int* __restrict__ tgt,
                                                  float* __restrict__ P,
                                                  float* __restrict__ Y,
                                                  float* __restrict__ Hd) {
    int i = blockIdx.x * TPB + threadIdx.x;
    int x = i & 127, y = (i >> 7) & 127, z = (i >> 14) & 63, b = i >> 20;
    int rem = i & (VOL - 1);
    const float* nb = net + (size_t)b * (2 * VOL);

    float c0 = nb[rem];
    float c1 = nb[rem + VOL];
    int   t  = tgt[i];
    float yv = (t > 0) ? 1.f : 0.f;

    float m  = fmaxf(c0, c1);
    float e0 = expf(c0 - m), e1 = expf(c1 - m);
    float s  = e0 + e1;
    float p  = e1 / s;
    float lse = m + logf(s);
    float nll = lse - ((t != 0) ? c1 : c0);
    float hv  = (p > 0.5f) ? 1.f : 0.f;
    float cn  = fabsf(((c0 > 0.5f) ? 1.f : 0.f) - yv) +
                fabsf(((c1 > 0.5f) ? 1.f : 0.f) - yv);

    P[i] = p; Y[i] = yv; Hd[i] = hv;

    float gpx = 0.f, gpy = 0.f, gpz = 0.f, gtx = 0.f, gty = 0.f, gtz = 0.f;
#pragma unroll
    for (int dz = -1; dz <= 1; ++dz) {
        if ((unsigned)(z + dz) >= DIMZ) continue;
        float sa = (dz == 0) ? 2.f : 1.f;
        float fdz = (float)dz;
#pragma unroll
        for (int dy = -1; dy <= 1; ++dy) {
            if ((unsigned)(y + dy) >= DIMY) continue;
            float sh = (dy == 0) ? 2.f : 1.f;
#pragma unroll
            for (int dx = -1; dx <= 1; ++dx) {
                if ((unsigned)(x + dx) >= DIMX) continue;
                int off = dz * SZ + dy * SY + dx;
                float vp = nb[rem + off];
                float vt = (tgt[i + off] > 0) ? 1.f : 0.f;
                float fdx = (float)dx;
                float sw  = (dx == 0) ? 2.f : 1.f;
                gpx += vp * sh * fdx;
                gpy += vp * sa * fdx;
                gpz += vp * sw * fdz;
                gtx += vt * sh * fdx;
                gty += vt * sa * fdx;
                gtz += vt * sw * fdz;
            }
        }
    }
    float dot  = gpx * gtx + gpy * gty + gpz * gtz;
    float np   = sqrtf(gpx * gpx + gpy * gpy + gpz * gpz);
    float nt   = sqrtf(gtx * gtx + gty * gty + gtz * gtz);
    float invp = 1.f / fmaxf(np, 1e-12f);
    float invt = 1.f / fmaxf(nt, 1e-12f);
    float den  = fmaxf((np * invp) * (nt * invt), 1e-8f);
    float ratio = (dot * invp * invt) / den;

    block_add((double)p,        &g_acc[0]);
    block_add((double)yv,       &g_acc[1]);
    block_add((double)(p * yv), &g_acc[2]);
    block_add((double)nll,      &g_acc[3]);
    block_add((double)cn,       &g_acc[4]);
    block_add((double)ratio,    &g_acc[5]);
}

// ---------------------------------------------------------------- FUSED skel iteration (SMEM halo)
// E = erode(img); open = dilate(E); delta = relu(img - open); skel update.
// Tile 32x8x8, halo 2. +INF img padding (erode clamp), -INF erode at
// out-of-volume (dilate clamp).
// Tiles per image = 4x * 16y * 8z * 2batch = 1024. grid = 3 * 1024.
#define SK_HX 36
#define SK_HY 12
#define SK_HZ 12
__global__ void __launch_bounds__(TPB) k_skel_fused(const float* __restrict__ in0,
                                                    const float* __restrict__ in1,
                                                    const float* __restrict__ in2,
                                                    float* __restrict__ E0,
                                                    float* __restrict__ E1,
                                                    float* __restrict__ E2,
                                                    float* __restrict__ sk0,
                                                    float* __restrict__ sk1,
                                                    float* __restrict__ sk2,
                                                    int first, int store_E) {
    __shared__ float sImg[SK_HZ * SK_HY * SK_HX];   // 5184 floats
    __shared__ float sEr [SK_HZ * SK_HY * SK_HX];
    int bid = blockIdx.x;
    int r = bid >> 10;
    int tile = bid & 1023;
    const float* img = (r == 0) ? in0 : (r == 1) ? in1 : in2;
    float* E  = (r == 0) ? E0 : (r == 1) ? E1 : E2;
    float* sk = (r == 0) ? sk0 : (r == 1) ? sk1 : sk2;
    int tx0 = (tile & 3) << 5;           // 4 x-tiles * 32
    int ty0 = ((tile >> 2) & 15) << 3;   // 16 y-tiles * 8
    int tz0 = ((tile >> 6) & 7) << 3;    // 8 z-tiles * 8
    int gb  = (tile >> 9) << 20;         // batch offset (*VOL)
    int t = threadIdx.x;

    // load img tile + halo2 (+INF outside volume)
    for (int idx = t; idx < SK_HZ * SK_HY * SK_HX; idx += TPB) {
        int lz = idx / (SK_HY * SK_HX);
        int rem = idx - lz * (SK_HY * SK_HX);
        int ly = rem / SK_HX, lx = rem - ly * SK_HX;
        int gx = tx0 + lx - 2, gy = ty0 + ly - 2, gz = tz0 + lz - 2;
        float v = PINF;
        if ((unsigned)gx < 128u && (unsigned)gy < 128u && (unsigned)gz < 64u)
            v = img[gb + gz * SZ + gy * SY + gx];
        sImg[idx] = v;
    }
    __syncthreads();

    // erode (7-point cross) on halo-1 region: 34 x 10 x 10
    for (int idx = t; idx < 34 * 10 * 10; idx += TPB) {
        int lz = idx / 340;
        int rem = idx - lz * 340;
        int ly = rem / 34, lx = rem - ly * 34;
        lx += 1; ly += 1; lz += 1;
        int gx = tx0 + lx - 2, gy = ty0 + ly - 2, gz = tz0 + lz - 2;
        float v = NINF;   // out-of-volume -> -INF so dilate ignores
        if ((unsigned)gx < 128u && (unsigned)gy < 128u && (unsigned)gz < 64u) {
            int c = (lz * SK_HY + ly) * SK_HX + lx;
            v = sImg[c];
            v = fminf(v, sImg[c - 1]);       v = fminf(v, sImg[c + 1]);
            v = fminf(v, sImg[c - SK_HX]);   v = fminf(v, sImg[c + SK_HX]);
            v = fminf(v, sImg[c - SK_HY * SK_HX]); v = fminf(v, sImg[c + SK_HY * SK_HX]);
        }
        sEr[(lz * SK_HY + ly) * SK_HX + lx] = v;
    }
    __syncthreads();

    // outputs: 32 x 8 x 8 = 2048
    for (int idx = t; idx < 2048; idx += TPB) {
        int ox = idx & 31, oy = (idx >> 5) & 7, oz = idx >> 8;
        int lx = ox + 2, ly = oy + 2, lz = oz + 2;
        int c = (lz * SK_HY + ly) * SK_HX + lx;
        float e = sEr[c];
        float o = NINF;
#pragma unroll
        for (int dz = -1; dz <= 1; ++dz)
#pragma unroll
            for (int dy = -1; dy <= 1; ++dy) {
                int b0 = c + dz * (SK_HY * SK_HX) + dy * SK_HX;
                o = fmaxf(o, fmaxf(sEr[b0 - 1], fmaxf(sEr[b0], sEr[b0 + 1])));
            }
        int g = gb + (tz0 + oz) * SZ + (ty0 + oy) * SY + (tx0 + ox);
        if (store_E) E[g] = e;
        float ic = sImg[c];
        float delta = fmaxf(ic - o, 0.f);
        float s = first ? 0.f : sk[g];
        sk[g] = s + fmaxf(delta - s * delta, 0.f);
    }
}

// ---------------------------------------------------------------- FUSED EDT: 3 minpool steps per kernel
// acc += cur + pool(cur) + pool^2(cur); nxt = pool^3(cur).
// Tile 32x8x4, halo 3. +INF padding (min clamp semantics).
// Tiles per mask = 4x * 16y * 16z * 2batch = 2048. grid = 2 * 2048.
#define ED_HX 38
#define ED_HY 14
#define ED_HZ 10
__global__ void __launch_bounds__(TPB) k_edt3(const float* __restrict__ cur0,
                                              const float* __restrict__ cur1,
                                              float* __restrict__ acc0,
                                              float* __restrict__ acc1,
                                              float* __restrict__ nxt0,
                                              float* __restrict__ nxt1,
                                              int first) {
    __shared__ float sA[ED_HZ * ED_HY * ED_HX];   // 5320 floats
    __shared__ float sB[ED_HZ * ED_HY * ED_HX];
    int bid = blockIdx.x;
    int r = bid >> 11;
    int tile = bid & 2047;
    const float* cur = r ? cur1 : cur0;
    float* acc = r ? acc1 : acc0;
    float* nxt = r ? nxt1 : nxt0;
    int tx0 = (tile & 3) << 5;           // 4 x-tiles * 32
    int ty0 = ((tile >> 2) & 15) << 3;   // 16 y-tiles * 8
    int tz0 = ((tile >> 6) & 15) << 2;   // 16 z-tiles * 4
    int gb  = (tile >> 10) << 20;        // batch offset (*VOL)
    int t = threadIdx.x;

    // load cur tile + halo3 (+INF outside volume)
    for (int idx = t; idx < ED_HZ * ED_HY * ED_HX; idx += TPB) {
        int lz = idx / (ED_HY * ED_HX);
        int rem = idx - lz * (ED_HY * ED_HX);
        int ly = rem / ED_HX, lx = rem - ly * ED_HX;
        int gx = tx0 + lx - 3, gy = ty0 + ly - 3, gz = tz0 + lz - 3;
        float v = PINF;
        if ((unsigned)gx < 128u && (unsigned)gy < 128u && (unsigned)gz < 64u)
            v = cur[gb + gz * SZ + gy * SY + gx];
        sA[idx] = v;
    }
    __syncthreads();

    // p1 = minpool27(sA) into sB on halo-2 region: 36 x 12 x 8
    for (int idx = t; idx < 36 * 12 * 8; idx += TPB) {
        int lz = idx / 432;
        int rem = idx - lz * 432;
        int ly = rem / 36, lx = rem - ly * 36;
        lx += 1; ly += 1; lz += 1;
        int gx = tx0 + lx - 3, gy = ty0 + ly - 3, gz = tz0 + lz - 3;
        float v = PINF;
        if ((unsigned)gx < 128u && (unsigned)gy < 128u && (unsigned)gz < 64u) {
#pragma unroll
            for (int dz = -1; dz <= 1; ++dz)
#pragma unroll
                for (int dy = -1; dy <= 1; ++dy) {
                    int b0 = ((lz + dz) * ED_HY + (ly + dy)) * ED_HX + lx;
                    v = fminf(v, fminf(sA[b0 - 1], fminf(sA[b0], sA[b0 + 1])));
                }
        }
        sB[(lz * ED_HY + ly) * ED_HX + lx] = v;
    }
    __syncthreads();

    // grab cur + p1 at centers before sA is overwritten
    float sum[4];
#pragma unroll
    for (int k = 0; k < 4; ++k) {
        int idx = t + k * TPB;            // 1024 outputs
        int ox = idx & 31, oy = (idx >> 5) & 7, oz = idx >> 8;
        int c = ((oz + 3) * ED_HY + (oy + 3)) * ED_HX + (ox + 3);
        sum[k] = sA[c] + sB[c];
    }
    __syncthreads();

    // p2 = minpool27(sB) into sA on halo-1 region: 34 x 10 x 6
    for (int idx = t; idx < 34 * 10 * 6; idx += TPB) {
        int lz = idx / 340;
        int rem = idx - lz * 340;
        int ly = rem / 34, lx = rem - ly * 34;
        lx += 2; ly += 2; lz += 2;
        int gx = tx0 + lx - 3, gy = ty0 + ly - 3, gz = tz0 + lz - 3;
        float v = PINF;
        if ((unsigned)gx < 128u && (unsigned)gy < 128u && (unsigned)gz < 64u) {
#pragma unroll
            for (int dz = -1; dz <= 1; ++dz)
#pragma unroll
                for (int dy = -1; dy <= 1; ++dy) {
                    int b0 = ((lz + dz) * ED_HY + (ly + dy)) * ED_HX + lx;
                    v = fminf(v, fminf(sB[b0 - 1], fminf(sB[b0], sB[b0 + 1])));
                }
        }
        sA[(lz * ED_HY + ly) * ED_HX + lx] = v;
    }
    __syncthreads();

    // p3 = minpool27(p2) at centers; write acc and nxt
#pragma unroll
    for (int k = 0; k < 4; ++k) {
        int idx = t + k * TPB;
        int ox = idx & 31, oy = (idx >> 5) & 7, oz = idx >> 8;
        int lx = ox + 3, ly = oy + 3, lz = oz + 3;
        int c = (lz * ED_HY + ly) * ED_HX + lx;
        float a2 = sA[c];
        float v = PINF;
#pragma unroll
        for (int dz = -1; dz <= 1; ++dz)
#pragma unroll
            for (int dy = -1; dy <= 1; ++dy) {
                int b0 = c + dz * (ED_HY * ED_HX) + dy * ED_HX;
                v = fminf(v, fminf(sA[b0 - 1], fminf(sA[b0], sA[b0 + 1])));
            }
        int g = gb + (tz0 + oz) * SZ + (ty0 + oy) * SY + (tx0 + ox);
        float tot = sum[k] + a2;
        acc[g] = first ? tot : (acc[g] + tot);
        nxt[g] = v;
    }
}

// ---------------------------------------------------------------- radius reductions + clDice sums (float4)
__global__ void __launch_bounds__(TPB) k_radius(const float* __restrict__ P,
                                                const float* __restrict__ Y,
                                                const float* __restrict__ Hd,
                                                const float* __restrict__ S1,
                                                const float* __restrict__ S2,
                                                const float* __restrict__ S3,
                                                const float* __restrict__ D1,
                                                const float* __restrict__ D2,
                                                const float* __restrict__ C1,
                                                const float* __restrict__ C2) {
    int i4 = blockIdx.x * TPB + threadIdx.x;
    int b = i4 >> 18;
    float4 yv = ((const float4*)Y)[i4];
    float4 p  = ((const float4*)P)[i4];
    float4 h  = ((const float4*)Hd)[i4];
    float4 s1 = ((const float4*)S1)[i4];
    float4 s2 = ((const float4*)S2)[i4];
    float4 s3 = ((const float4*)S3)[i4];
    float4 d1 = ((const float4*)D1)[i4];
    float4 d2 = ((const float4*)D2)[i4];
    float4 c1 = ((const float4*)C1)[i4];
    float4 c2 = ((const float4*)C2)[i4];

    float4 sr_t, sr_p;
    {
        float s3p, sb;
        sr_t.x = (d1.x + c1.x) * yv.x * s2.x;
        sr_t.y = (d1.y + c1.y) * yv.y * s2.y;
        sr_t.z = (d1.z + c1.z) * yv.z * s2.z;
        sr_t.w = (d1.w + c1.w) * yv.w * s2.w;
        s3p = s3.x * p.x; sb = (s3p > 0.5f) ? 1.f : 0.f; sr_p.x = (d2.x + c2.x) * h.x * sb;
        s3p = s3.y * p.y; sb = (s3p > 0.5f) ? 1.f : 0.f; sr_p.y = (d2.y + c2.y) * h.y * sb;
        s3p = s3.z * p.z; sb = (s3p > 0.5f) ? 1.f : 0.f; sr_p.z = (d2.z + c2.z) * h.z * sb;
        s3p = s3.w * p.w; sb = (s3p > 0.5f) ? 1.f : 0.f; sr_p.w = (d2.w + c2.w) * h.w * sb;
    }

    block_max_to(hmax4(sr_t), &g_mm[0 + b]);
    block_min_to(hmin4(sr_t), &g_mm[2 + b]);
    block_max_to(hmax4(sr_p), &g_mm[4 + b]);
    block_min_to(hmin4(sr_p), &g_mm[6 + b]);

    double sum_s1  = (double)s1.x + s1.y + s1.z + s1.w;
    double sum_s1y = (double)(s1.x * yv.x) + (s1.y * yv.y) + (s1.z * yv.z) + (s1.w * yv.w);
    double sum_s2  = (double)s2.x + s2.y + s2.z + s2.w;
    double sum_s2p = (double)(s2.x * p.x) + (s2.y * p.y) + (s2.z * p.z) + (s2.w * p.w);
    block_add(sum_s1,  &g_acc[6]);
    block_add(sum_s1y, &g_acc[7]);
    block_add(sum_s2,  &g_acc[8]);
    block_add(sum_s2p, &g_acc[9]);
}

// ---------------------------------------------------------------- union-loss sums (float4)
__global__ void __launch_bounds__(TPB) k_unionloss(const float* __restrict__ P,
                                                   const float* __restrict__ Y,
                                                   const float* __restrict__ Hd,
                                                   const float* __restrict__ S2,
                                                   const float* __restrict__ S3,
                                                   const float* __restrict__ D1,
                                                   const float* __restrict__ D2,
                                                   const float* __restrict__ C1,
                                                   const float* __restrict__ C2) {
    int i4 = blockIdx.x * TPB + threadIdx.x;
    int b = i4 >> 18;
    float rmax_t = fmaxf(__uint_as_float(g_mm[0 + b]), 1.f);
    float rmin_t = fmaxf(__uint_as_float(g_mm[2 + b]), 1.f);
    float rmax_p = fmaxf(__uint_as_float(g_mm[4 + b]), 1.f);
    float rmin_p = fmaxf(__uint_as_float(g_mm[6 + b]), 1.f);

    float4 yv = ((const float4*)Y)[i4];
    float4 p  = ((const float4*)P)[i4];
    float4 h  = ((const float4*)Hd)[i4];
    float4 s2 = ((const float4*)S2)[i4];
    float4 s3 = ((const float4*)S3)[i4];
    float4 d1 = ((const float4*)D1)[i4];
    float4 d2 = ((const float4*)D2)[i4];
    float4 c1 = ((const float4*)C1)[i4];
    float4 c2 = ((const float4*)C2)[i4];

    double inter1 = 0.0, uni1 = 0.0, inter2 = 0.0, uni2 = 0.0;
    const float* yvp = &yv.x;  const float* pp  = &p.x;
    const float* hp  = &h.x;   const float* s2p_ = &s2.x;
    const float* s3p_ = &s3.x; const float* d1p = &d1.x;
    const float* d2p = &d2.x;  const float* c1p = &c1.x;
    const float* c2p = &c2.x;
#pragma unroll
    for (int k = 0; k < 4; ++k) {
        float yvk = yvp[k], pk = pp[k], hk = hp[k], s2k = s2p_[k];
        float s3pk = s3p_[k] * pk;

        float dist_t = (d1p[k] + c1p[k]) * yvk;
        float sr_t   = dist_t * s2k;
        float q_vl   = fminf(dist_t, rmax_t) / rmax_t * yvk;
        float It     = (rmax_t - sr_t + rmin_t) / rmax_t;
        float q_sl   = It * It * s2k * s2k;

        float sb     = (s3pk > 0.5f) ? 1.f : 0.f;
        float dist_p = (d2p[k] + c2p[k]) * hk;
        float sr_p   = dist_p * sb;
        float q_vp   = fminf(dist_p, rmax_p) / rmax_p * pk;
        float Ip     = (rmax_p - sr_p + rmin_p) / rmax_p;
        float q_sp   = Ip * Ip * sb * s3pk;

        inter1 += (double)(q_sp * powf(q_sp + 1e-4f, 0.7f) * q_vl);
        uni1   += (double)(q_sp * (0.1f * q_sp + 0.9f * q_vl));
        inter2 += (double)(q_sl * powf(q_vp + 1e-4f, 0.7f) * q_sl);
        uni2   += (double)(q_sl * (0.1f * q_vp + 0.9f * q_sl));
    }

    block_add(inter1, &g_acc[10]);
    block_add(uni1,   &g_acc[11]);
    block_add(inter2, &g_acc[12]);
    block_add(uni2,   &g_acc[13]);
}

// ---------------------------------------------------------------- final combine
__global__ void k_final(float* __restrict__ out) {
    double Nd = (double)NTOT;
    double sum_p = g_acc[0], sum_y = g_acc[1], tp = g_acc[2];
    double dice = -((2.0 * tp + 1e-5) / (sum_p + sum_y + 1e-5));
    double ce   = g_acc[3] / Nd;
    double conn = g_acc[4] / (2.0 * Nd);
    double dirl = 1.0 - g_acc[5] / Nd;
    double tprec = (g_acc[7] + 1.0) / (g_acc[6] + 1.0);
    double tsens = (g_acc[9] + 1.0) / (g_acc[8] + 1.0);
    double cl = 1.0 - 2.0 * tprec * tsens / (tprec + tsens);
    double u1 = 1.0 - (g_acc[10] + 1.0) / (g_acc[11] + 1.0);
    double u2 = 1.0 - (g_acc[12] + 1.0) / (g_acc[13] + 1.0);
    out[0] = (float)(dice + ce + cl + dirl + conn + u1 + u2);
}

// ---------------------------------------------------------------- host orchestration
extern "C" void kernel_launch(void* const* d_in, const int* in_sizes, int n_in,
                              void* d_out, int out_size) {
    const float* net = (const float*)d_in[0];
    const int*   tgt = (const int*)d_in[1];

    void* bp = nullptr;
    cudaGetSymbolAddress(&bp, g_buf);
    float* B   = (float*)bp;
    float* P   = B + 0ull  * NTOT;
    float* Y   = B + 1ull  * NTOT;
    float* Hd  = B + 2ull  * NTOT;
    float* S1  = B + 3ull  * NTOT;
    float* S2  = B + 4ull  * NTOT;
    float* S3  = B + 5ull  * NTOT;
    float* EA0 = B + 6ull  * NTOT;
    float* EA1 = B + 7ull  * NTOT;
    float* EA2 = B + 8ull  * NTOT;
    float* EB0 = B + 9ull  * NTOT;
    float* EB1 = B + 10ull * NTOT;
    float* EB2 = B + 11ull * NTOT;
    float* D1  = B + 15ull * NTOT;
    float* D2  = B + 16ull * NTOT;

    k_init<<<1, 32>>>();
    k_prep_dir<<<NBLK, TPB>>>(net, tgt, P, Y, Hd);

    // --- three soft_skel chains, one fused kernel per iteration ---
    {
        const float* img[3] = {P, Y, Hd};
        float* pa[3] = {EA0, EA1, EA2};
        float* pb[3] = {EB0, EB1, EB2};
        for (int it = 0; it < 11; ++it) {
            float** E = (it & 1) ? pb : pa;
            int store_E = (it < 10) ? 1 : 0;
            k_skel_fused<<<3 * 1024, TPB>>>(img[0], img[1], img[2],
                                            E[0], E[1], E[2],
                                            S1, S2, S3,
                                            (it == 0) ? 1 : 0, store_E);
            img[0] = E[0]; img[1] = E[1]; img[2] = E[2];
        }
    }

    // --- two EDT chains, 3 pool steps per kernel (5 kernels = 15 steps) ---
    // acc = sum of terms 0..14; curl = pool^15 folded into consumers.
    const float* curl[2] = {Y, Hd};
    {
        float* pa[2] = {EA0, EA1};
        float* pb[2] = {EB0, EB1};
        for (int it = 0; it < 5; ++it) {
            float** nxt = (it & 1) ? pb : pa;
            k_edt3<<<2 * 2048, TPB>>>(curl[0], curl[1], D1, D2,
                                      nxt[0], nxt[1], (it == 0) ? 1 : 0);
            curl[0] = nxt[0]; curl[1] = nxt[1];
        }
    }

    k_radius<<<NBLK4, TPB>>>(P, Y, Hd, S1, S2, S3, D1, D2, curl[0], curl[1]);
    k_unionloss<<<NBLK4, TPB>>>(P, Y, Hd, S2, S3, D1, D2, curl[0], curl[1]);
    k_final<<<1, 1>>>((float*)d_out);
}